// round 6
// baseline (speedup 1.0000x reference)
#include <cuda_runtime.h>
#include <math.h>

#define D_DIM 131072
#define K_SEL 5
#define WARPS_PER_ROW 128             // 1024 elems per warp
#define TPB 256
#define MAX_B 128
#define NCAND (WARPS_PER_ROW * K_SEL) // 640 candidates per row
#define TOPK_CTAS_PER_B 16            // B*128 warps / 8 warps per CTA
#define FILL_CTAS_PER_B 10            // B*5*131072*4 bytes / 256KB
#define FILL_CHUNK_BYTES 262144       // 256KB per fill CTA
#define ZBUF_BYTES 16384              // 16KB smem zero buffer

// inter-kernel scratch (no allocations allowed)
__device__ unsigned long long g_cand[MAX_B * NCAND];

// monotonic float->uint transform (order-preserving incl. negatives)
__device__ __forceinline__ unsigned ford(float f) {
    unsigned u = __float_as_uint(f);
    return u ^ (((int)u >> 31) | 0x80000000u);
}

// ---------------------------------------------------------------------------
// Kernel 1: heterogeneous. Low blockIdx = top-k stage1 CTAs (read stream),
// high blockIdx = TMA zero-fill CTAs (write stream). Both streams coexist
// on HBM -> phase time ~ total bytes / BW instead of serial sum.
// ---------------------------------------------------------------------------
__global__ void fused_topk_fill(const float* __restrict__ sims,
                                float* __restrict__ out,
                                int idx_off, int B) {
    __shared__ float4 zbuf[ZBUF_BYTES / 16];
    const int t = threadIdx.x;
    const int topk_ctas = B * TOPK_CTAS_PER_B;

    if ((int)blockIdx.x >= topk_ctas) {
        // ---------------- fill role ----------------
        const int fid = blockIdx.x - topk_ctas;
        const float4 z = make_float4(0.f, 0.f, 0.f, 0.f);
#pragma unroll
        for (int i = t; i < ZBUF_BYTES / 16; i += TPB) zbuf[i] = z;
        __syncthreads();
        asm volatile("fence.proxy.async.shared::cta;" ::: "memory");

        char* dst = (char*)(out + idx_off) + (long long)fid * FILL_CHUNK_BYTES;
        if (t < 16) {
            unsigned saddr = (unsigned)__cvta_generic_to_shared(zbuf);
            asm volatile(
                "cp.async.bulk.global.shared::cta.bulk_group [%0], [%1], %2;"
                :: "l"(dst + t * ZBUF_BYTES), "r"(saddr), "r"(ZBUF_BYTES)
                : "memory");
            asm volatile("cp.async.bulk.commit_group;" ::: "memory");
            asm volatile("cp.async.bulk.wait_group 0;" ::: "memory");
        }
        return;
    }

    // ---------------- top-k stage1 role ----------------
    const int gw   = (blockIdx.x * TPB + t) >> 5;
    const int lane = t & 31;
    const int b    = gw / WARPS_PER_ROW;
    const int w    = gw % WARPS_PER_ROW;
    const int base = w * 1024;
    const float4* p = reinterpret_cast<const float4*>(
        sims + (size_t)b * D_DIM + base);

    // 8 back-to-back LDG.128 (MLP=8)
    float4 r[8];
#pragma unroll
    for (int i = 0; i < 8; i++) r[i] = p[lane + i * 32];

    float c[32];
#pragma unroll
    for (int i = 0; i < 8; i++) {
        c[4*i+0] = r[i].x; c[4*i+1] = r[i].y;
        c[4*i+2] = r[i].z; c[4*i+3] = r[i].w;
    }

    // per-thread argmax; ids increase with e, strict > keeps lowest idx
    float bv = -INFINITY; int bi = 0x7fffffff; int be = 0;
#pragma unroll
    for (int i = 0; i < 8; i++)
#pragma unroll
        for (int q = 0; q < 4; q++) {
            const int e = 4*i + q;
            if (c[e] > bv) {
                bv = c[e]; bi = base + ((lane + i*32) << 2) + q; be = e;
            }
        }

    unsigned dead = 0u;
#pragma unroll
    for (int rr = 0; rr < K_SEL; rr++) {
        float wv = bv; int wi = bi;
#pragma unroll
        for (int off = 16; off >= 1; off >>= 1) {
            float ov = __shfl_down_sync(0xffffffffu, wv, off);
            int   oi = __shfl_down_sync(0xffffffffu, wi, off);
            if (ov > wv || (ov == wv && oi < wi)) { wv = ov; wi = oi; }
        }
        wv = __shfl_sync(0xffffffffu, wv, 0);
        wi = __shfl_sync(0xffffffffu, wi, 0);

        if (lane == rr)
            g_cand[(b * WARPS_PER_ROW + w) * K_SEL + rr] =
                ((unsigned long long)ford(wv) << 32) | (unsigned)(~wi);

        if (bi == wi) {                   // exactly one lane owns the winner
            dead |= (1u << be);
            bv = -INFINITY; bi = 0x7fffffff; be = 0;
#pragma unroll
            for (int i = 0; i < 8; i++)
#pragma unroll
                for (int q = 0; q < 4; q++) {
                    const int e = 4*i + q;
                    float val = ((dead >> e) & 1u) ? -INFINITY : c[e];
                    if (val > bv) {
                        bv = val; bi = base + ((lane + i*32) << 2) + q; be = e;
                    }
                }
        }
    }
}

// ---------------------------------------------------------------------------
// Kernel 2: warp-per-row merge of 640 packed candidates -> float-cast index
// front region (fully written, no memset needed) + one-hot patches.
// ---------------------------------------------------------------------------
__global__ void topk_finalize(float* __restrict__ out, int idx_off, int B) {
    const int warp = (blockIdx.x * blockDim.x + threadIdx.x) >> 5;
    const int lane = threadIdx.x & 31;
    if (warp >= B) return;
    const int b = warp;

    unsigned long long k[20];
#pragma unroll
    for (int s = 0; s < 20; s++)
        k[s] = g_cand[b * NCAND + lane + s * 32];

    unsigned dead = 0u;
#pragma unroll
    for (int rr = 0; rr < K_SEL; rr++) {
        unsigned long long bk = 0ull; int bs = 0;
#pragma unroll
        for (int s = 0; s < 20; s++) {
            bool live = !((dead >> s) & 1u);
            if (live && k[s] > bk) { bk = k[s]; bs = s; }
        }
        unsigned long long wk = bk;
#pragma unroll
        for (int off = 16; off >= 1; off >>= 1) {
            unsigned long long ok = __shfl_down_sync(0xffffffffu, wk, off);
            if (ok > wk) wk = ok;
        }
        wk = __shfl_sync(0xffffffffu, wk, 0);
        if (bk == wk) dead |= (1u << bs);   // packed keys unique -> one winner

        if (lane == 0) {
            int idx = (int)(~(unsigned)wk);
            if (idx_off > 0) out[b * K_SEL + rr] = (float)idx;
            out[(size_t)idx_off + ((size_t)b * K_SEL + rr) * D_DIM + idx] = 1.0f;
        }
    }
}

extern "C" void kernel_launch(void* const* d_in, const int* in_sizes, int n_in,
                              void* d_out, int out_size) {
    const float* sims = (const float*)d_in[0];
    int B = in_sizes[0] / D_DIM;
    if (B < 1) B = 1;
    if (B > MAX_B) B = MAX_B;

    long long soft = (long long)B * K_SEL * D_DIM;
    long long idx_off_ll = (long long)out_size - soft;
    int idx_off = (idx_off_ll > 0) ? (int)idx_off_ll : 0;

    float* outf = (float*)d_out;

    // 1) fused: top-k candidates (read stream) + zero fill (write stream)
    int grid = B * (TOPK_CTAS_PER_B + FILL_CTAS_PER_B);
    fused_topk_fill<<<grid, TPB>>>(sims, outf, idx_off, B);

    // 2) final merge + index front region + one-hot patches
    topk_finalize<<<(B * 32 + 255) / 256, 256>>>(outf, idx_off, B);
}

// round 7
// speedup vs baseline: 1.2403x; 1.2403x over previous
#include <cuda_runtime.h>
#include <math.h>

#define D_DIM 131072
#define K_SEL 5
#define WARPS_PER_ROW 128             // 1024 elems per warp
#define TPB 256
#define MAX_B 128
#define NCAND (WARPS_PER_ROW * K_SEL) // 640 candidates per row
#define CTAS_PER_B 16                 // 128 warps / 8 warps per CTA
#define ZBUF_BYTES 16384              // 16KB smem zero buffer
// per-CTA fill slice: (K_SEL * D_DIM * 4 bytes) / CTAS_PER_B = 163840 = 10 x 16KB
#define FILL_SLICE_BYTES (K_SEL * D_DIM * 4 / CTAS_PER_B)
#define FILL_OPS (FILL_SLICE_BYTES / ZBUF_BYTES)   // 10

// inter-kernel scratch (no allocations allowed)
__device__ unsigned long long g_cand[MAX_B * NCAND];

// monotonic float->uint transform (order-preserving incl. negatives)
__device__ __forceinline__ unsigned ford(float f) {
    unsigned u = __float_as_uint(f);
    return u ^ (((int)u >> 31) | 0x80000000u);
}

// ---------------------------------------------------------------------------
// Kernel 1: every CTA issues its async TMA zero-fill slice FIRST (write
// stream drains in background), then does its top-k segment (read stream).
// Within-CTA async overlap -> no dependence on CTA scheduling order.
// ---------------------------------------------------------------------------
__global__ void fused_topk_fill(const float* __restrict__ sims,
                                float* __restrict__ out,
                                int idx_off) {
    __shared__ float4 zbuf[ZBUF_BYTES / 16];
    const int t = threadIdx.x;

    // ---- zero the smem staging buffer (4 x STS.128 per thread) ----
    const float4 z = make_float4(0.f, 0.f, 0.f, 0.f);
#pragma unroll
    for (int i = t; i < ZBUF_BYTES / 16; i += TPB) zbuf[i] = z;
    __syncthreads();
    asm volatile("fence.proxy.async.shared::cta;" ::: "memory");

    // ---- issue async fill: FILL_OPS x 16KB bulk stores (threads 0..9) ----
    char* dst = (char*)(out + idx_off) +
                (long long)blockIdx.x * FILL_SLICE_BYTES;
    if (t < FILL_OPS) {
        unsigned saddr = (unsigned)__cvta_generic_to_shared(zbuf);
        asm volatile(
            "cp.async.bulk.global.shared::cta.bulk_group [%0], [%1], %2;"
            :: "l"(dst + t * ZBUF_BYTES), "r"(saddr), "r"(ZBUF_BYTES)
            : "memory");
        asm volatile("cp.async.bulk.commit_group;" ::: "memory");
    }

    // ---------------- top-k stage1 (overlaps with TMA drain) ----------------
    const int gw   = (blockIdx.x * TPB + t) >> 5;
    const int lane = t & 31;
    const int b    = gw / WARPS_PER_ROW;
    const int w    = gw % WARPS_PER_ROW;
    const int base = w * 1024;
    const float4* p = reinterpret_cast<const float4*>(
        sims + (size_t)b * D_DIM + base);

    // 8 back-to-back LDG.128 (MLP=8)
    float4 r[8];
#pragma unroll
    for (int i = 0; i < 8; i++) r[i] = p[lane + i * 32];

    float c[32];
#pragma unroll
    for (int i = 0; i < 8; i++) {
        c[4*i+0] = r[i].x; c[4*i+1] = r[i].y;
        c[4*i+2] = r[i].z; c[4*i+3] = r[i].w;
    }

    // per-thread argmax; ids increase with e, strict > keeps lowest idx
    float bv = -INFINITY; int bi = 0x7fffffff; int be = 0;
#pragma unroll
    for (int i = 0; i < 8; i++)
#pragma unroll
        for (int q = 0; q < 4; q++) {
            const int e = 4*i + q;
            if (c[e] > bv) {
                bv = c[e]; bi = base + ((lane + i*32) << 2) + q; be = e;
            }
        }

    unsigned dead = 0u;
#pragma unroll
    for (int rr = 0; rr < K_SEL; rr++) {
        float wv = bv; int wi = bi;
#pragma unroll
        for (int off = 16; off >= 1; off >>= 1) {
            float ov = __shfl_down_sync(0xffffffffu, wv, off);
            int   oi = __shfl_down_sync(0xffffffffu, wi, off);
            if (ov > wv || (ov == wv && oi < wi)) { wv = ov; wi = oi; }
        }
        wv = __shfl_sync(0xffffffffu, wv, 0);
        wi = __shfl_sync(0xffffffffu, wi, 0);

        if (lane == rr)
            g_cand[(b * WARPS_PER_ROW + w) * K_SEL + rr] =
                ((unsigned long long)ford(wv) << 32) | (unsigned)(~wi);

        if (bi == wi) {                   // exactly one lane owns the winner
            dead |= (1u << be);
            bv = -INFINITY; bi = 0x7fffffff; be = 0;
#pragma unroll
            for (int i = 0; i < 8; i++)
#pragma unroll
                for (int q = 0; q < 4; q++) {
                    const int e = 4*i + q;
                    float val = ((dead >> e) & 1u) ? -INFINITY : c[e];
                    if (val > bv) {
                        bv = val; bi = base + ((lane + i*32) << 2) + q; be = e;
                    }
                }
        }
    }

    // ---- drain this CTA's fill stores before exit ----
    if (t < FILL_OPS)
        asm volatile("cp.async.bulk.wait_group 0;" ::: "memory");
}

// ---------------------------------------------------------------------------
// Kernel 2: warp-per-row merge of 640 packed candidates -> float-cast index
// front region (fully written, no memset needed) + one-hot patches.
// ---------------------------------------------------------------------------
__global__ void topk_finalize(float* __restrict__ out, int idx_off, int B) {
    const int warp = (blockIdx.x * blockDim.x + threadIdx.x) >> 5;
    const int lane = threadIdx.x & 31;
    if (warp >= B) return;
    const int b = warp;

    unsigned long long k[20];
#pragma unroll
    for (int s = 0; s < 20; s++)
        k[s] = g_cand[b * NCAND + lane + s * 32];

    unsigned dead = 0u;
#pragma unroll
    for (int rr = 0; rr < K_SEL; rr++) {
        unsigned long long bk = 0ull; int bs = 0;
#pragma unroll
        for (int s = 0; s < 20; s++) {
            bool live = !((dead >> s) & 1u);
            if (live && k[s] > bk) { bk = k[s]; bs = s; }
        }
        unsigned long long wk = bk;
#pragma unroll
        for (int off = 16; off >= 1; off >>= 1) {
            unsigned long long ok = __shfl_down_sync(0xffffffffu, wk, off);
            if (ok > wk) wk = ok;
        }
        wk = __shfl_sync(0xffffffffu, wk, 0);
        if (bk == wk) dead |= (1u << bs);   // packed keys unique -> one winner

        if (lane == 0) {
            int idx = (int)(~(unsigned)wk);
            if (idx_off > 0) out[b * K_SEL + rr] = (float)idx;
            out[(size_t)idx_off + ((size_t)b * K_SEL + rr) * D_DIM + idx] = 1.0f;
        }
    }
}

extern "C" void kernel_launch(void* const* d_in, const int* in_sizes, int n_in,
                              void* d_out, int out_size) {
    const float* sims = (const float*)d_in[0];
    int B = in_sizes[0] / D_DIM;
    if (B < 1) B = 1;
    if (B > MAX_B) B = MAX_B;

    long long soft = (long long)B * K_SEL * D_DIM;
    long long idx_off_ll = (long long)out_size - soft;
    int idx_off = (idx_off_ll > 0) ? (int)idx_off_ll : 0;

    float* outf = (float*)d_out;

    // 1) fused: async TMA zero-fill slice + top-k candidates per CTA
    fused_topk_fill<<<B * CTAS_PER_B, TPB>>>(sims, outf, idx_off);

    // 2) final merge + index front region + one-hot patches
    topk_finalize<<<(B * 32 + 255) / 256, 256>>>(outf, idx_off, B);
}

// round 8
// speedup vs baseline: 1.2993x; 1.0475x over previous
#include <cuda_runtime.h>
#include <math.h>

#define D_DIM 131072
#define K_SEL 5
#define WARPS_PER_ROW 128             // 1024 elems per warp
#define TPB 256
#define MAX_B 128
#define NCAND (WARPS_PER_ROW * K_SEL) // 640 candidates per row
#define CTAS_PER_B 16                 // 128 warps / 8 warps per CTA
#define ZBUF_BYTES 16384              // 16KB smem zero buffer
// per-CTA fill slice: (K_SEL * D_DIM * 4 bytes) / CTAS_PER_B = 163840 = 10 x 16KB
#define FILL_SLICE_BYTES (K_SEL * D_DIM * 4 / CTAS_PER_B)
#define FILL_OPS (FILL_SLICE_BYTES / ZBUF_BYTES)   // 10

// inter-CTA scratch (no allocations allowed)
__device__ unsigned long long g_cand[MAX_B * NCAND];
__device__ int g_arrive[MAX_B];   // zero-initialized; self-resetting per replay

// monotonic float->uint transform (order-preserving incl. negatives)
__device__ __forceinline__ unsigned ford(float f) {
    unsigned u = __float_as_uint(f);
    return u ^ (((int)u >> 31) | 0x80000000u);
}

// ---------------------------------------------------------------------------
// Single fused kernel:
//   1. issue async TMA zero-fill slice (write stream drains in background)
//   2. warp-level top-5 over this CTA's 8K-element segment (read stream)
//   3. drain TMA, fence, atomic ticket per row; the 16th (last) CTA of a row
//      merges all 640 candidates, writes index floats, patches one-hots.
// ---------------------------------------------------------------------------
__global__ void fused_topk_fill(const float* __restrict__ sims,
                                float* __restrict__ out,
                                int idx_off) {
    __shared__ float4 zbuf[ZBUF_BYTES / 16];
    __shared__ unsigned long long s_warp[8];
    __shared__ unsigned long long s_win;
    __shared__ int s_last;
    const int t = threadIdx.x;
    const int b_row = blockIdx.x / CTAS_PER_B;

    // ---- zero the smem staging buffer ----
    const float4 z = make_float4(0.f, 0.f, 0.f, 0.f);
#pragma unroll
    for (int i = t; i < ZBUF_BYTES / 16; i += TPB) zbuf[i] = z;
    __syncthreads();
    asm volatile("fence.proxy.async.shared::cta;" ::: "memory");

    // ---- issue async fill: FILL_OPS x 16KB bulk stores (threads 0..9) ----
    char* dst = (char*)(out + idx_off) +
                (long long)blockIdx.x * FILL_SLICE_BYTES;
    if (t < FILL_OPS) {
        unsigned saddr = (unsigned)__cvta_generic_to_shared(zbuf);
        asm volatile(
            "cp.async.bulk.global.shared::cta.bulk_group [%0], [%1], %2;"
            :: "l"(dst + t * ZBUF_BYTES), "r"(saddr), "r"(ZBUF_BYTES)
            : "memory");
        asm volatile("cp.async.bulk.commit_group;" ::: "memory");
    }

    // ---------------- top-k stage1 (overlaps with TMA drain) ----------------
    const int gw   = (blockIdx.x * TPB + t) >> 5;
    const int lane = t & 31;
    const int w    = gw % WARPS_PER_ROW;
    const int base = w * 1024;
    const float4* p = reinterpret_cast<const float4*>(
        sims + (size_t)b_row * D_DIM + base);

    // 8 back-to-back LDG.128 (MLP=8)
    float4 r[8];
#pragma unroll
    for (int i = 0; i < 8; i++) r[i] = p[lane + i * 32];

    float c[32];
#pragma unroll
    for (int i = 0; i < 8; i++) {
        c[4*i+0] = r[i].x; c[4*i+1] = r[i].y;
        c[4*i+2] = r[i].z; c[4*i+3] = r[i].w;
    }

    // per-thread argmax; ids increase with e, strict > keeps lowest idx
    float bv = -INFINITY; int bi = 0x7fffffff; int be = 0;
#pragma unroll
    for (int i = 0; i < 8; i++)
#pragma unroll
        for (int q = 0; q < 4; q++) {
            const int e = 4*i + q;
            if (c[e] > bv) {
                bv = c[e]; bi = base + ((lane + i*32) << 2) + q; be = e;
            }
        }

    unsigned dead = 0u;
#pragma unroll
    for (int rr = 0; rr < K_SEL; rr++) {
        float wv = bv; int wi = bi;
#pragma unroll
        for (int off = 16; off >= 1; off >>= 1) {
            float ov = __shfl_down_sync(0xffffffffu, wv, off);
            int   oi = __shfl_down_sync(0xffffffffu, wi, off);
            if (ov > wv || (ov == wv && oi < wi)) { wv = ov; wi = oi; }
        }
        wv = __shfl_sync(0xffffffffu, wv, 0);
        wi = __shfl_sync(0xffffffffu, wi, 0);

        if (lane == rr)
            g_cand[(b_row * WARPS_PER_ROW + w) * K_SEL + rr] =
                ((unsigned long long)ford(wv) << 32) | (unsigned)(~wi);

        if (bi == wi) {                   // exactly one lane owns the winner
            dead |= (1u << be);
            bv = -INFINITY; bi = 0x7fffffff; be = 0;
#pragma unroll
            for (int i = 0; i < 8; i++)
#pragma unroll
                for (int q = 0; q < 4; q++) {
                    const int e = 4*i + q;
                    float val = ((dead >> e) & 1u) ? -INFINITY : c[e];
                    if (val > bv) {
                        bv = val; bi = base + ((lane + i*32) << 2) + q; be = e;
                    }
                }
        }
    }

    // ---- drain this CTA's fill stores, publish, take row ticket ----
    if (t < FILL_OPS) {
        asm volatile("cp.async.bulk.wait_group 0;" ::: "memory");
    }
    __syncthreads();
    __threadfence();                      // publish g_cand + fill completion
    if (t == 0)
        s_last = (atomicAdd(&g_arrive[b_row], 1) == CTAS_PER_B - 1);
    __syncthreads();
    if (!s_last) return;

    // =============== last CTA of this row: merge + scatter ===============
    __threadfence();                      // acquire other CTAs' writes

    // thread t holds candidates t, t+256, (t+512 if t<128); 0 = dead
    unsigned long long c0 = g_cand[b_row * NCAND + t];
    unsigned long long c1 = g_cand[b_row * NCAND + t + 256];
    unsigned long long c2 = (t < NCAND - 512)
        ? g_cand[b_row * NCAND + t + 512] : 0ull;

    const int wid = t >> 5;
#pragma unroll
    for (int rr = 0; rr < K_SEL; rr++) {
        unsigned long long m = c0;
        if (c1 > m) m = c1;
        if (c2 > m) m = c2;
#pragma unroll
        for (int off = 16; off >= 1; off >>= 1) {
            unsigned long long o = __shfl_down_sync(0xffffffffu, m, off);
            if (o > m) m = o;
        }
        if (lane == 0) s_warp[wid] = m;
        __syncthreads();
        if (t < 32) {
            unsigned long long f = (lane < 8) ? s_warp[lane] : 0ull;
#pragma unroll
            for (int off = 4; off >= 1; off >>= 1) {
                unsigned long long o = __shfl_down_sync(0xffffffffu, f, off);
                if (o > f) f = o;
            }
            if (lane == 0) s_win = f;
        }
        __syncthreads();
        unsigned long long win = s_win;
        // kill the winner (packed keys are unique per row)
        if (c0 == win) c0 = 0ull;
        if (c1 == win) c1 = 0ull;
        if (c2 == win) c2 = 0ull;
        if (t == 0) {
            int idx = (int)(~(unsigned)win);
            if (idx_off > 0) out[b_row * K_SEL + rr] = (float)idx;
            out[(size_t)idx_off + ((size_t)b_row * K_SEL + rr) * D_DIM + idx]
                = 1.0f;
        }
        __syncthreads();
    }

    if (t == 0) g_arrive[b_row] = 0;      // reset for next graph replay
}

extern "C" void kernel_launch(void* const* d_in, const int* in_sizes, int n_in,
                              void* d_out, int out_size) {
    const float* sims = (const float*)d_in[0];
    int B = in_sizes[0] / D_DIM;
    if (B < 1) B = 1;
    if (B > MAX_B) B = MAX_B;

    long long soft = (long long)B * K_SEL * D_DIM;
    long long idx_off_ll = (long long)out_size - soft;
    int idx_off = (idx_off_ll > 0) ? (int)idx_off_ll : 0;

    fused_topk_fill<<<B * CTAS_PER_B, TPB>>>(sims, (float*)d_out, idx_off);
}

// round 9
// speedup vs baseline: 1.3013x; 1.0016x over previous
#include <cuda_runtime.h>
#include <math.h>

#define D_DIM 131072
#define K_SEL 5
#define ELEMS 16                      // elements per thread (512 per warp)
#define WARPS_PER_ROW 256             // D_DIM / 512
#define TPB 256
#define MAX_B 128
#define NCAND (WARPS_PER_ROW * K_SEL) // 1280 candidates per row
#define CTAS_PER_B 32                 // 256 warps / 8 warps per CTA
#define ZBUF_BYTES 16384              // 16KB smem zero buffer
// per-CTA fill slice: (K_SEL * D_DIM * 4) / CTAS_PER_B = 81920 = 5 x 16KB
#define FILL_SLICE_BYTES (K_SEL * D_DIM * 4 / CTAS_PER_B)
#define FILL_OPS (FILL_SLICE_BYTES / ZBUF_BYTES)   // 5

// inter-CTA scratch (no allocations allowed)
__device__ unsigned long long g_cand[MAX_B * NCAND];
__device__ int g_arrive[MAX_B];   // zero-initialized; self-resetting per replay

// monotonic float->uint transform (order-preserving incl. negatives)
__device__ __forceinline__ unsigned ford(float f) {
    unsigned u = __float_as_uint(f);
    return u ^ (((int)u >> 31) | 0x80000000u);
}

// element id e (0..15) -> global index within the row
__device__ __forceinline__ int eidx(int base, int lane, int e) {
    // e = 4*i + q ; idx = base + ((lane + i*32) << 2) + q
    return base + ((lane + (e >> 2) * 32) << 2) + (e & 3);
}

// ---------------------------------------------------------------------------
// Single fused kernel:
//   1. issue async TMA zero-fill slice (write stream drains in background)
//   2. warp-level top-5 over this CTA's 4K-element segment (read stream)
//   3. drain TMA, fence, atomic ticket per row; the 32nd (last) CTA of a row
//      merges all 1280 candidates, writes index floats, patches one-hots.
// ---------------------------------------------------------------------------
__global__ void __launch_bounds__(TPB, 3)
fused_topk_fill(const float* __restrict__ sims,
                float* __restrict__ out,
                int idx_off) {
    __shared__ float4 zbuf[ZBUF_BYTES / 16];
    __shared__ unsigned long long s_warp[8];
    __shared__ unsigned long long s_win;
    __shared__ int s_last;
    const int t = threadIdx.x;
    const int b_row = blockIdx.x / CTAS_PER_B;

    // ---- zero the smem staging buffer ----
    const float4 z = make_float4(0.f, 0.f, 0.f, 0.f);
#pragma unroll
    for (int i = t; i < ZBUF_BYTES / 16; i += TPB) zbuf[i] = z;
    __syncthreads();
    asm volatile("fence.proxy.async.shared::cta;" ::: "memory");

    // ---- issue async fill: FILL_OPS x 16KB bulk stores (threads 0..4) ----
    char* dst = (char*)(out + idx_off) +
                (long long)blockIdx.x * FILL_SLICE_BYTES;
    if (t < FILL_OPS) {
        unsigned saddr = (unsigned)__cvta_generic_to_shared(zbuf);
        asm volatile(
            "cp.async.bulk.global.shared::cta.bulk_group [%0], [%1], %2;"
            :: "l"(dst + t * ZBUF_BYTES), "r"(saddr), "r"(ZBUF_BYTES)
            : "memory");
        asm volatile("cp.async.bulk.commit_group;" ::: "memory");
    }

    // ---------------- top-k stage1 (overlaps with TMA drain) ----------------
    const int gw   = (blockIdx.x * TPB + t) >> 5;
    const int lane = t & 31;
    const int w    = gw % WARPS_PER_ROW;
    const int base = w * (ELEMS * 32);       // 512 elems per warp
    const float4* p = reinterpret_cast<const float4*>(
        sims + (size_t)b_row * D_DIM + base);

    // 4 back-to-back LDG.128
    float4 r[4];
#pragma unroll
    for (int i = 0; i < 4; i++) r[i] = p[lane + i * 32];

    float c[ELEMS];
#pragma unroll
    for (int i = 0; i < 4; i++) {
        c[4*i+0] = r[i].x; c[4*i+1] = r[i].y;
        c[4*i+2] = r[i].z; c[4*i+3] = r[i].w;
    }

    // per-thread argmax over 16 elems: track value + 4-bit element id only.
    // e increases with global index, so strict > keeps the lowest index.
    float bv = -INFINITY; int be = 0;
#pragma unroll
    for (int e = 0; e < ELEMS; e++)
        if (c[e] > bv) { bv = c[e]; be = e; }
    int bi = eidx(base, lane, be);

    unsigned dead = 0u;
#pragma unroll
    for (int rr = 0; rr < K_SEL; rr++) {
        float wv = bv; int wi = bi;
#pragma unroll
        for (int off = 16; off >= 1; off >>= 1) {
            float ov = __shfl_down_sync(0xffffffffu, wv, off);
            int   oi = __shfl_down_sync(0xffffffffu, wi, off);
            if (ov > wv || (ov == wv && oi < wi)) { wv = ov; wi = oi; }
        }
        wv = __shfl_sync(0xffffffffu, wv, 0);
        wi = __shfl_sync(0xffffffffu, wi, 0);

        if (lane == rr)
            g_cand[(b_row * WARPS_PER_ROW + w) * K_SEL + rr] =
                ((unsigned long long)ford(wv) << 32) | (unsigned)(~wi);

        if (bi == wi) {                   // exactly one lane owns the winner
            dead |= (1u << be);
            bv = -INFINITY; be = 0;
#pragma unroll
            for (int e = 0; e < ELEMS; e++) {
                float val = ((dead >> e) & 1u) ? -INFINITY : c[e];
                if (val > bv) { bv = val; be = e; }
            }
            bi = eidx(base, lane, be);
        }
    }

    // ---- drain this CTA's fill stores, publish, take row ticket ----
    if (t < FILL_OPS)
        asm volatile("cp.async.bulk.wait_group 0;" ::: "memory");
    __syncthreads();
    __threadfence();                      // publish g_cand + fill completion
    if (t == 0)
        s_last = (atomicAdd(&g_arrive[b_row], 1) == CTAS_PER_B - 1);
    __syncthreads();
    if (!s_last) return;

    // =============== last CTA of this row: merge + scatter ===============
    __threadfence();                      // acquire other CTAs' writes

    // thread t holds candidates t + s*256, s=0..4 ; 0 = dead
    unsigned long long k[5];
#pragma unroll
    for (int s = 0; s < 5; s++)
        k[s] = g_cand[b_row * NCAND + t + s * 256];

    const int wid = t >> 5;
#pragma unroll
    for (int rr = 0; rr < K_SEL; rr++) {
        unsigned long long m = k[0];
#pragma unroll
        for (int s = 1; s < 5; s++) if (k[s] > m) m = k[s];
#pragma unroll
        for (int off = 16; off >= 1; off >>= 1) {
            unsigned long long o = __shfl_down_sync(0xffffffffu, m, off);
            if (o > m) m = o;
        }
        if (lane == 0) s_warp[wid] = m;
        __syncthreads();
        if (t < 32) {
            unsigned long long f = (lane < 8) ? s_warp[lane] : 0ull;
#pragma unroll
            for (int off = 4; off >= 1; off >>= 1) {
                unsigned long long o = __shfl_down_sync(0xffffffffu, f, off);
                if (o > f) f = o;
            }
            if (lane == 0) s_win = f;
        }
        __syncthreads();
        unsigned long long win = s_win;
#pragma unroll
        for (int s = 0; s < 5; s++) if (k[s] == win) k[s] = 0ull;
        if (t == 0) {
            int idx = (int)(~(unsigned)win);
            if (idx_off > 0) out[b_row * K_SEL + rr] = (float)idx;
            out[(size_t)idx_off + ((size_t)b_row * K_SEL + rr) * D_DIM + idx]
                = 1.0f;
        }
        __syncthreads();
    }

    if (t == 0) g_arrive[b_row] = 0;      // reset for next graph replay
}

extern "C" void kernel_launch(void* const* d_in, const int* in_sizes, int n_in,
                              void* d_out, int out_size) {
    const float* sims = (const float*)d_in[0];
    int B = in_sizes[0] / D_DIM;
    if (B < 1) B = 1;
    if (B > MAX_B) B = MAX_B;

    long long soft = (long long)B * K_SEL * D_DIM;
    long long idx_off_ll = (long long)out_size - soft;
    int idx_off = (idx_off_ll > 0) ? (int)idx_off_ll : 0;

    fused_topk_fill<<<B * CTAS_PER_B, TPB>>>(sims, (float*)d_out, idx_off);
}